// round 9
// baseline (speedup 1.0000x reference)
#include <cuda_runtime.h>
#include <cuda_bf16.h>
#include <cstdint>

// ---------------------------------------------------------------------------
// ProtoTSNet on GB300 — round 9
//  - gemm: 2 CTAs/SM (smaller tiles M{128,80}xN128, 2-tap phases, <=128 regs)
//
// out[0..319]    = logits [32,10]
// out[320..6719] = min_distances [32,200]
// ---------------------------------------------------------------------------

#define B_     32
#define FIN    16
#define L_     8192
#define LAT    64
#define L1_    8190
#define P_     200
#define KP     16
#define LO     8175
#define C_     10
#define EPS_   1e-4f
#define TPAD   8224

// ---------------- static device scratch (allocation-free) -----------------
__device__ __nv_bfloat16 d_fT[B_ * TPAD * LAT];    // f [b][t][c], bf16
__device__ float         d_g [B_ * TPAD];          // sum_c f_bf16^2
__device__ __nv_bfloat16 d_protA[16 * 256 * LAT];  // protos [kk][p pad256][c]
__device__ float         d_p2[256];                // ||p||^2 (bf16-rounded)
__device__ __nv_bfloat16 d_w1[3 * 64 * 32];        // enc w  [tap][ch][16hi|16lo]
__device__ __nv_bfloat16 d_w2[64 * 128];           // addon w [ch2][64hi|64lo]

__device__ __forceinline__ uint32_t smem_u32(const void* p) {
    uint32_t a;
    asm("{ .reg .u64 t; cvta.to.shared.u64 t, %1; cvt.u32.u64 %0, t; }"
        : "=r"(a) : "l"(p));
    return a;
}
__device__ __forceinline__ void cp16(uint32_t s, const void* g) {
    asm volatile("cp.async.cg.shared.global [%0], [%1], 16;" :: "r"(s), "l"(g));
}
#define CP_COMMIT() asm volatile("cp.async.commit_group;" ::: "memory")
#define CP_WAIT0()  asm volatile("cp.async.wait_group 0;" ::: "memory")

__device__ __forceinline__ void mma16816(float* c, const uint32_t* a,
                                         const uint32_t* b)
{
    asm volatile(
        "mma.sync.aligned.m16n8k16.row.col.f32.bf16.bf16.f32 "
        "{%0,%1,%2,%3}, {%4,%5,%6,%7}, {%8,%9}, {%0,%1,%2,%3};"
        : "+f"(c[0]), "+f"(c[1]), "+f"(c[2]), "+f"(c[3])
        : "r"(a[0]), "r"(a[1]), "r"(a[2]), "r"(a[3]), "r"(b[0]), "r"(b[1]));
}
#define LDSM4(r0, r1, r2, r3, addr)                                           \
    asm volatile("ldmatrix.sync.aligned.m8n8.x4.shared.b16 {%0,%1,%2,%3},[%4];" \
        : "=r"(r0), "=r"(r1), "=r"(r2), "=r"(r3) : "r"(addr))

// ---------------------------------------------------------------------------
// Kernel 0: merged prep (block-range dispatch)
// ---------------------------------------------------------------------------
#define PREP_GRID 1305

__global__ void prep_kernel(const float* __restrict__ protos,
                            const float* __restrict__ ew,
                            const float* __restrict__ aw,
                            unsigned* __restrict__ md)
{
    const int blk = blockIdx.x;
    const int tid = threadIdx.x;

    if (blk < 1024) {                              // protA
        int idx = blk * 256 + tid;
        int c  = idx & 63;
        int pp = (idx >> 6) & 255;
        int kk = idx >> 14;
        float v = (pp < P_) ? protos[pp * (LAT * KP) + c * KP + kk] : 0.f;
        d_protA[idx] = __float2bfloat16(v);
    } else if (blk < 1224) {                       // p2
        const int p = blk - 1024;
        float s = 0.f;
        for (int i = tid; i < LAT * KP; i += 256) {
            float v = __bfloat162float(__float2bfloat16(protos[p * LAT * KP + i]));
            s += v * v;
        }
#pragma unroll
        for (int o = 16; o; o >>= 1) s += __shfl_xor_sync(0xffffffffu, s, o);
        __shared__ float red[8];
        if ((tid & 31) == 0) red[tid >> 5] = s;
        __syncthreads();
        if (tid == 0) {
            float ts = 0.f;
            for (int w = 0; w < 8; w++) ts += red[w];
            d_p2[p] = ts;
        }
    } else if (blk < 1249) {                       // init md
        int i = (blk - 1224) * 256 + tid;
        if (i < B_ * P_) md[i] = 0x7f800000u;
    } else if (blk < 1273) {                       // prep_w1
        int idx = (blk - 1249) * 256 + tid;
        if (idx < 3 * 64 * 32) {
            int pos = idx & 31, ch = (idx >> 5) & 63, tap = idx >> 11;
            int i = pos & 15;
            float w = ew[ch * 48 + i * 3 + tap];
            __nv_bfloat16 hi = __float2bfloat16(w);
            if (pos < 16) d_w1[idx] = hi;
            else          d_w1[idx] = __float2bfloat16(w - __bfloat162float(hi));
        }
    } else {                                       // prep_w2
        int idx = (blk - 1273) * 256 + tid;
        if (idx < 64 * 128) {
            int pos = idx & 127, ch2 = idx >> 7;
            int c = pos & 63;
            float w = aw[ch2 * 64 + c];
            __nv_bfloat16 hi = __float2bfloat16(w);
            if (pos < 64) d_w2[idx] = hi;
            else          d_w2[idx] = __float2bfloat16(w - __bfloat162float(hi));
        }
    }
}

// ---------------------------------------------------------------------------
// Kernel 1: enc conv(k=3)+ReLU + addon 1x1+ReLU via HMMA (split-bf16 3-pass)
// ---------------------------------------------------------------------------
#define B1_ROWB 80
#define OFF_B1  0
#define OFF_A1  20800
#define OFF_A2  36160
#define OFF_B2  53568
#define ENC_DYN 123200

__global__ void __launch_bounds__(256, 1)
enc_addon_kernel(const float* __restrict__ x)
{
    extern __shared__ char esm[];
    __shared__ float s_g2[256];

    const int b   = blockIdx.y;
    const int t0  = blockIdx.x * 256;
    const int tid = threadIdx.x;
    const int lane = tid & 31;
    const int wid  = tid >> 5;
    const int wm  = wid & 3;
    const int wn  = wid >> 2;
    const int sub = lane >> 3;
    const int lr  = lane & 7;
    const int g   = lane >> 2;
    const int tig = lane & 3;

    const uint32_t b1_u = smem_u32(esm) + OFF_B1;
    const uint32_t a1_u = smem_u32(esm) + OFF_A1;
    const uint32_t a2_u = smem_u32(esm) + OFF_A2;
    const uint32_t b2_u = smem_u32(esm) + OFF_B2;

    for (int idx = tid; idx < 16 * 260; idx += 256) {
        int i = idx / 260, r = idx - i * 260;
        int t = t0 + r;
        float v = (t < L_ && r < 258) ? x[(b * FIN + i) * L_ + t] : 0.f;
        __nv_bfloat16 hi = __float2bfloat16(v);
        __nv_bfloat16 lo = __float2bfloat16(v - __bfloat162float(hi));
        char* row = esm + OFF_B1 + r * B1_ROWB;
        *reinterpret_cast<__nv_bfloat16*>(row + i * 2)      = hi;
        *reinterpret_cast<__nv_bfloat16*>(row + 32 + i * 2) = lo;
    }
    for (int idx = tid; idx < 3 * 64 * 16; idx += 256) {
        int q = idx & 15, ch = (idx >> 4) & 63, tap = idx >> 10;
        *reinterpret_cast<uint32_t*>(esm + OFF_A1 + tap * (64 * B1_ROWB)
                                     + ch * B1_ROWB + q * 4) =
            reinterpret_cast<const uint32_t*>(d_w1)[idx];
    }
    for (int idx = tid; idx < 64 * 64; idx += 256) {
        int q = idx & 63, ch2 = idx >> 6;
        *reinterpret_cast<uint32_t*>(esm + OFF_A2 + ch2 * 272 + q * 4) =
            reinterpret_cast<const uint32_t*>(d_w2)[idx];
    }
    if (tid < 256) s_g2[tid] = 0.f;
    __syncthreads();

    // ---- stage 1: conv k=3 ----
    float acc1[4][4][4];
#pragma unroll
    for (int mt = 0; mt < 4; mt++)
#pragma unroll
        for (int nt = 0; nt < 4; nt++)
#pragma unroll
            for (int e = 0; e < 4; e++) acc1[mt][nt][e] = 0.f;

    const uint32_t a1row = (uint32_t)(wm * 64 + (sub & 1) * 8 + lr);
    const uint32_t a1colq = (uint32_t)((sub >> 1) * 16);
    const uint32_t w1row = (uint32_t)((wn * 32 + (sub >> 1) * 8 + lr) * B1_ROWB
                                      + (sub & 1) * 16);

#pragma unroll
    for (int tap = 0; tap < 3; tap++) {
#pragma unroll
        for (int pass = 0; pass < 3; pass++) {
            const uint32_t colA = (pass == 2) ? 32u : 0u;
            const uint32_t colB = (pass == 1) ? 32u : 0u;
            uint32_t bf[4][2];
            const uint32_t wb = a1_u + tap * (64 * B1_ROWB) + w1row + colB;
            LDSM4(bf[0][0], bf[0][1], bf[1][0], bf[1][1], wb);
            LDSM4(bf[2][0], bf[2][1], bf[3][0], bf[3][1], wb + 16 * B1_ROWB);
#pragma unroll
            for (int mt = 0; mt < 4; mt++) {
                uint32_t a[4];
                LDSM4(a[0], a[1], a[2], a[3],
                      b1_u + (a1row + mt * 16 + tap) * B1_ROWB + a1colq + colA);
#pragma unroll
                for (int nt = 0; nt < 4; nt++)
                    mma16816(acc1[mt][nt], a, bf[nt]);
            }
        }
    }

    // ---- epilogue 1 ----
#pragma unroll
    for (int mt = 0; mt < 4; mt++) {
#pragma unroll
        for (int nt = 0; nt < 4; nt++) {
#pragma unroll
            for (int eh = 0; eh < 2; eh++) {
                const int t  = wm * 64 + mt * 16 + g + eh * 8;
                const int ch = wn * 32 + nt * 8 + tig * 2;
                float v0 = fmaxf(acc1[mt][nt][eh * 2 + 0], 0.f);
                float v1 = fmaxf(acc1[mt][nt][eh * 2 + 1], 0.f);
                __nv_bfloat16 h0 = __float2bfloat16(v0);
                __nv_bfloat16 h1 = __float2bfloat16(v1);
                __nv_bfloat16 l0 = __float2bfloat16(v0 - __bfloat162float(h0));
                __nv_bfloat16 l1 = __float2bfloat16(v1 - __bfloat162float(h1));
                uint32_t hp = (uint32_t)__bfloat16_as_ushort(h0)
                            | ((uint32_t)__bfloat16_as_ushort(h1) << 16);
                uint32_t lp = (uint32_t)__bfloat16_as_ushort(l0)
                            | ((uint32_t)__bfloat16_as_ushort(l1) << 16);
                char* row = esm + OFF_B2 + t * 272;
                *reinterpret_cast<uint32_t*>(row + ch * 2)       = hp;
                *reinterpret_cast<uint32_t*>(row + 128 + ch * 2) = lp;
            }
        }
    }
    __syncthreads();

    // ---- stage 2: 1x1 addon ----
    float acc2[4][4][4];
#pragma unroll
    for (int mt = 0; mt < 4; mt++)
#pragma unroll
        for (int nt = 0; nt < 4; nt++)
#pragma unroll
            for (int e = 0; e < 4; e++) acc2[mt][nt][e] = 0.f;

    const uint32_t a2base = b2_u + (uint32_t)((wm * 64 + (sub & 1) * 8 + lr) * 272
                                              + (sub >> 1) * 16);
    const uint32_t w2base = a2_u + (uint32_t)((wn * 32 + (sub >> 1) * 8 + lr) * 272
                                              + (sub & 1) * 16);

#pragma unroll
    for (int step = 0; step < 12; step++) {
        const int kc   = step & 3;
        const int pass = step >> 2;
        const uint32_t colA = (pass == 2) ? (128u + kc * 32u) : (kc * 32u);
        const uint32_t colB = (pass == 1) ? (128u + kc * 32u) : (kc * 32u);
        uint32_t bf[4][2];
        LDSM4(bf[0][0], bf[0][1], bf[1][0], bf[1][1], w2base + colB);
        LDSM4(bf[2][0], bf[2][1], bf[3][0], bf[3][1], w2base + colB + 16 * 272);
#pragma unroll
        for (int mt = 0; mt < 4; mt++) {
            uint32_t a[4];
            LDSM4(a[0], a[1], a[2], a[3], a2base + mt * (16 * 272) + colA);
#pragma unroll
            for (int nt = 0; nt < 4; nt++)
                mma16816(acc2[mt][nt], a, bf[nt]);
        }
    }

    // ---- epilogue 2 ----
#pragma unroll
    for (int mt = 0; mt < 4; mt++) {
#pragma unroll
        for (int eh = 0; eh < 2; eh++) {
            const int t  = wm * 64 + mt * 16 + g + eh * 8;
            const int tg = t0 + t;
            float gp = 0.f;
#pragma unroll
            for (int nt = 0; nt < 4; nt++) {
                const int ch = wn * 32 + nt * 8 + tig * 2;
                float v0 = fmaxf(acc2[mt][nt][eh * 2 + 0], 0.f);
                float v1 = fmaxf(acc2[mt][nt][eh * 2 + 1], 0.f);
                __nv_bfloat162 h2 = __floats2bfloat162_rn(v0, v1);
                float r0 = __bfloat162float(__low2bfloat16(h2));
                float r1 = __bfloat162float(__high2bfloat16(h2));
                gp += r0 * r0 + r1 * r1;
                if (tg < L1_)
                    *reinterpret_cast<uint32_t*>(
                        d_fT + ((size_t)b * TPAD + tg) * LAT + ch) =
                        *reinterpret_cast<uint32_t*>(&h2);
            }
            atomicAdd(&s_g2[t], gp);
        }
    }
    __syncthreads();
    if (t0 + tid < L1_) d_g[b * TPAD + t0 + tid] = s_g2[tid];
}

// ---------------------------------------------------------------------------
// Kernel 2: HMMA GEMM + distance + min-reduce
//   templated on MB16 (CTA M rows: 128 or 80); CTA N = 128; 8 warps; 2 CTAs/SM
//   8 phases x 2 taps, cp.async double-buffered protos
// ---------------------------------------------------------------------------
#define NT_       128
#define FROWS     144
#define ROWB      144
#define SF_BYTES  (FROWS * ROWB)           // 20736

template<int MB16>
__global__ void __launch_bounds__(256, 2)
gemm_min_kernel(unsigned* __restrict__ md, int p0)
{
    constexpr int MBW = (MB16 == 128) ? 2 : 5;    // m16 blocks per warp
    constexpr int NTW = (MB16 == 128) ? 8 : 2;    // n8  blocks per warp
    constexpr int SP_TAPB   = MB16 * ROWB;
    constexpr int SP_BYTESB = 2 * SP_TAPB;        // 2 taps per phase
    constexpr int LD_ITEMS  = 2 * MB16 * 8;

    extern __shared__ char dynsm[];
    char* sf = dynsm;
    char* sp = dynsm + SF_BYTES;

    __shared__ float    s_g[FROWS + 16];
    __shared__ float    s2s[NT_];
    __shared__ float    s_p2[128];
    __shared__ unsigned s_md[128];

    const int b   = blockIdx.y;
    const int t0  = blockIdx.x * NT_;
    const int tid = threadIdx.x;
    const int lane = tid & 31;
    const int wid  = tid >> 5;
    const int wmb = (MB16 == 128) ? ((wid >> 1) * 32) : 0;     // warp M base
    const int wnb = (MB16 == 128) ? ((wid & 1) * 64) : (wid * 16); // warp N base
    const int sub = lane >> 3;
    const int lr  = lane & 7;

    const uint32_t sf_u32 = smem_u32(sf);
    const uint32_t sp_u32 = smem_u32(sp);

    const __nv_bfloat16* fT = d_fT + (size_t)b * TPAD * LAT;
    for (int i = tid; i < FROWS * 8; i += 256) {
        int r = i >> 3, seg = i & 7;
        cp16(sf_u32 + r * ROWB + seg * 16,
             fT + (size_t)(t0 + r) * LAT + seg * 8);
    }
    for (int i = tid; i < LD_ITEMS; i += 256) {
        int j = i / (MB16 * 8), rs = i % (MB16 * 8);
        int r = rs >> 3, seg = rs & 7;
        cp16(sp_u32 + j * SP_TAPB + r * ROWB + seg * 16,
             d_protA + ((size_t)(j * 256 + p0 + r)) * LAT + seg * 8);
    }
    CP_COMMIT();

    for (int i = tid; i < FROWS + 16; i += 256) s_g[i] = d_g[b * TPAD + t0 + i];
    if (tid < 128) {
        s_p2[tid] = d_p2[p0 + tid];
        s_md[tid] = 0x7f800000u;
    }
    CP_WAIT0();
    __syncthreads();

    if (tid < NT_) {
        float s = 0.f;
#pragma unroll
        for (int k = 0; k < KP; k++) s += s_g[tid + k];
        s2s[tid] = s;
    }

    float acc[MBW][NTW][4];
#pragma unroll
    for (int mt = 0; mt < MBW; mt++)
#pragma unroll
        for (int nt = 0; nt < NTW; nt++)
#pragma unroll
            for (int e = 0; e < 4; e++) acc[mt][nt][e] = 0.f;

    const uint32_t a_off = (uint32_t)((wmb + (sub & 1) * 8 + lr) * ROWB
                                      + (sub >> 1) * 16);
    const uint32_t b_off = (uint32_t)((wnb + (sub >> 1) * 8 + lr) * ROWB
                                      + (sub & 1) * 16);

    for (int ph = 0; ph < 8; ph++) {
        const uint32_t buf = sp_u32 + (ph & 1) * SP_BYTESB;

        if (ph < 7) {
            const uint32_t nbuf = sp_u32 + ((ph + 1) & 1) * SP_BYTESB;
            for (int i = tid; i < LD_ITEMS; i += 256) {
                int j = i / (MB16 * 8), rs = i % (MB16 * 8);
                int r = rs >> 3, seg = rs & 7;
                cp16(nbuf + j * SP_TAPB + r * ROWB + seg * 16,
                     d_protA + ((size_t)(((ph + 1) * 2 + j) * 256 + p0 + r)) * LAT
                             + seg * 8);
            }
            CP_COMMIT();
        }

#pragma unroll
        for (int j = 0; j < 2; j++) {
            const int kk = ph * 2 + j;
            const uint32_t abase = buf + j * SP_TAPB + a_off;
            const uint32_t bbase = sf_u32 + kk * ROWB + b_off;
#pragma unroll
            for (int cc = 0; cc < 4; cc++) {
                uint32_t a[MBW][4], bf[NTW][2];
#pragma unroll
                for (int mb = 0; mb < MBW; mb++)
                    LDSM4(a[mb][0], a[mb][1], a[mb][2], a[mb][3],
                          abase + mb * (16 * ROWB) + cc * 32);
#pragma unroll
                for (int np = 0; np < NTW / 2; np++)
                    LDSM4(bf[2*np][0], bf[2*np][1], bf[2*np+1][0], bf[2*np+1][1],
                          bbase + np * (16 * ROWB) + cc * 32);
#pragma unroll
                for (int mt = 0; mt < MBW; mt++)
#pragma unroll
                    for (int nt = 0; nt < NTW; nt++)
                        mma16816(acc[mt][nt], a[mt], bf[nt]);
            }
        }

        if (ph < 7) {
            CP_WAIT0();
            __syncthreads();
        }
    }

    // ---- epilogue: dist = relu(s2 - 2*xp + p2), min over t ----
    const int g   = lane >> 2;
    const int tig = lane & 3;
#pragma unroll
    for (int mt = 0; mt < MBW; mt++) {
#pragma unroll
        for (int half = 0; half < 2; half++) {
            const int pl = wmb + mt * 16 + g + half * 8;
            const float pp = s_p2[pl];
            float mn = __int_as_float(0x7f800000);
#pragma unroll
            for (int nt = 0; nt < NTW; nt++) {
#pragma unroll
                for (int e = 0; e < 2; e++) {
                    const int col = wnb + nt * 8 + tig * 2 + e;
                    if (t0 + col < LO) {
                        float xp = acc[mt][nt][half * 2 + e];
                        float dd = fmaxf(s2s[col] - 2.f * xp + pp, 0.f);
                        mn = fminf(mn, dd);
                    }
                }
            }
            atomicMin(&s_md[pl], __float_as_uint(mn));
        }
    }
    __syncthreads();
    if (tid < MB16 && p0 + tid < P_)
        atomicMin(&md[b * P_ + p0 + tid], s_md[tid]);
}

#define GEMM_DYN0 (SF_BYTES + 2 * 2 * 128 * ROWB)   // 94464
#define GEMM_DYN1 (SF_BYTES + 2 * 2 * 80  * ROWB)   // 66816

// ---------------------------------------------------------------------------
// Kernel 3: head — one block per batch, warp per class
// ---------------------------------------------------------------------------
__global__ void head_kernel(const float* __restrict__ lw,
                            float* __restrict__ out)
{
    __shared__ float acts[P_];
    const int b   = blockIdx.x;
    const int tid = threadIdx.x;     // 320
    const unsigned* mdb = (const unsigned*)(out + B_ * C_) + b * P_;

    if (tid < P_) {
        float m = __uint_as_float(mdb[tid]);
        acts[tid] = logf((m + 1.0f) / (m + EPS_));
    }
    __syncthreads();

    const int c    = tid >> 5;
    const int lane = tid & 31;
    float s = 0.f;
    for (int p = lane; p < P_; p += 32)
        s += acts[p] * lw[c * P_ + p];
#pragma unroll
    for (int o = 16; o; o >>= 1) s += __shfl_xor_sync(0xffffffffu, s, o);
    if (lane == 0) out[b * C_ + c] = s;
}

// ---------------------------------------------------------------------------
extern "C" void kernel_launch(void* const* d_in, const int* in_sizes, int n_in,
                              void* d_out, int out_size)
{
    const float* x       = (const float*)d_in[0];
    const float* enc_w   = (const float*)d_in[1];
    const float* addon_w = (const float*)d_in[2];
    const float* protos  = (const float*)d_in[3];
    const float* last_w  = (const float*)d_in[4];
    float* out = (float*)d_out;

    cudaFuncSetAttribute(enc_addon_kernel,
                         cudaFuncAttributeMaxDynamicSharedMemorySize, ENC_DYN);
    cudaFuncSetAttribute(gemm_min_kernel<128>,
                         cudaFuncAttributeMaxDynamicSharedMemorySize, GEMM_DYN0);
    cudaFuncSetAttribute(gemm_min_kernel<80>,
                         cudaFuncAttributeMaxDynamicSharedMemorySize, GEMM_DYN1);

    unsigned* md = (unsigned*)(out + B_ * C_);

    prep_kernel<<<PREP_GRID, 256>>>(protos, enc_w, addon_w, md);
    enc_addon_kernel<<<dim3(32, B_), 256, ENC_DYN>>>(x);
    gemm_min_kernel<128><<<dim3(64, B_), 256, GEMM_DYN0>>>(md, 0);    // p 0-127
    gemm_min_kernel<80> <<<dim3(64, B_), 256, GEMM_DYN1>>>(md, 128);  // p 128-199
    head_kernel<<<B_, 320>>>(last_w, out);
}

// round 10
// speedup vs baseline: 1.0981x; 1.0981x over previous
#include <cuda_runtime.h>
#include <cuda_bf16.h>
#include <cstdint>

// ---------------------------------------------------------------------------
// ProtoTSNet on GB300 — round 10
//  - gemm: reverted to round-8 config (measured best: M-split 128/80, N=256)
//  - enc: t-tile 128, warp tile 32x32, 78KB smem -> 2 CTAs/SM
//
// out[0..319]    = logits [32,10]
// out[320..6719] = min_distances [32,200]
// ---------------------------------------------------------------------------

#define B_     32
#define FIN    16
#define L_     8192
#define LAT    64
#define L1_    8190
#define P_     200
#define KP     16
#define LO     8175
#define C_     10
#define EPS_   1e-4f
#define TPAD   8224

// ---------------- static device scratch (allocation-free) -----------------
__device__ __nv_bfloat16 d_fT[B_ * TPAD * LAT];    // f [b][t][c], bf16
__device__ float         d_g [B_ * TPAD];          // sum_c f_bf16^2
__device__ __nv_bfloat16 d_protA[16 * 256 * LAT];  // protos [kk][p pad256][c]
__device__ float         d_p2[256];                // ||p||^2 (bf16-rounded)
__device__ __nv_bfloat16 d_w1[3 * 64 * 32];        // enc w  [tap][ch][16hi|16lo]
__device__ __nv_bfloat16 d_w2[64 * 128];           // addon w [ch2][64hi|64lo]

__device__ __forceinline__ uint32_t smem_u32(const void* p) {
    uint32_t a;
    asm("{ .reg .u64 t; cvta.to.shared.u64 t, %1; cvt.u32.u64 %0, t; }"
        : "=r"(a) : "l"(p));
    return a;
}
__device__ __forceinline__ void cp16(uint32_t s, const void* g) {
    asm volatile("cp.async.cg.shared.global [%0], [%1], 16;" :: "r"(s), "l"(g));
}
#define CP_COMMIT() asm volatile("cp.async.commit_group;" ::: "memory")
#define CP_WAIT0()  asm volatile("cp.async.wait_group 0;" ::: "memory")

__device__ __forceinline__ void mma16816(float* c, const uint32_t* a,
                                         const uint32_t* b)
{
    asm volatile(
        "mma.sync.aligned.m16n8k16.row.col.f32.bf16.bf16.f32 "
        "{%0,%1,%2,%3}, {%4,%5,%6,%7}, {%8,%9}, {%0,%1,%2,%3};"
        : "+f"(c[0]), "+f"(c[1]), "+f"(c[2]), "+f"(c[3])
        : "r"(a[0]), "r"(a[1]), "r"(a[2]), "r"(a[3]), "r"(b[0]), "r"(b[1]));
}
#define LDSM4(r0, r1, r2, r3, addr)                                           \
    asm volatile("ldmatrix.sync.aligned.m8n8.x4.shared.b16 {%0,%1,%2,%3},[%4];" \
        : "=r"(r0), "=r"(r1), "=r"(r2), "=r"(r3) : "r"(addr))

// ---------------------------------------------------------------------------
// Kernel 0: merged prep (block-range dispatch)
// ---------------------------------------------------------------------------
#define PREP_GRID 1305

__global__ void prep_kernel(const float* __restrict__ protos,
                            const float* __restrict__ ew,
                            const float* __restrict__ aw,
                            unsigned* __restrict__ md)
{
    const int blk = blockIdx.x;
    const int tid = threadIdx.x;

    if (blk < 1024) {                              // protA
        int idx = blk * 256 + tid;
        int c  = idx & 63;
        int pp = (idx >> 6) & 255;
        int kk = idx >> 14;
        float v = (pp < P_) ? protos[pp * (LAT * KP) + c * KP + kk] : 0.f;
        d_protA[idx] = __float2bfloat16(v);
    } else if (blk < 1224) {                       // p2
        const int p = blk - 1024;
        float s = 0.f;
        for (int i = tid; i < LAT * KP; i += 256) {
            float v = __bfloat162float(__float2bfloat16(protos[p * LAT * KP + i]));
            s += v * v;
        }
#pragma unroll
        for (int o = 16; o; o >>= 1) s += __shfl_xor_sync(0xffffffffu, s, o);
        __shared__ float red[8];
        if ((tid & 31) == 0) red[tid >> 5] = s;
        __syncthreads();
        if (tid == 0) {
            float ts = 0.f;
            for (int w = 0; w < 8; w++) ts += red[w];
            d_p2[p] = ts;
        }
    } else if (blk < 1249) {                       // init md
        int i = (blk - 1224) * 256 + tid;
        if (i < B_ * P_) md[i] = 0x7f800000u;
    } else if (blk < 1273) {                       // prep_w1
        int idx = (blk - 1249) * 256 + tid;
        if (idx < 3 * 64 * 32) {
            int pos = idx & 31, ch = (idx >> 5) & 63, tap = idx >> 11;
            int i = pos & 15;
            float w = ew[ch * 48 + i * 3 + tap];
            __nv_bfloat16 hi = __float2bfloat16(w);
            if (pos < 16) d_w1[idx] = hi;
            else          d_w1[idx] = __float2bfloat16(w - __bfloat162float(hi));
        }
    } else {                                       // prep_w2
        int idx = (blk - 1273) * 256 + tid;
        if (idx < 64 * 128) {
            int pos = idx & 127, ch2 = idx >> 7;
            int c = pos & 63;
            float w = aw[ch2 * 64 + c];
            __nv_bfloat16 hi = __float2bfloat16(w);
            if (pos < 64) d_w2[idx] = hi;
            else          d_w2[idx] = __float2bfloat16(w - __bfloat162float(hi));
        }
    }
}

// ---------------------------------------------------------------------------
// Kernel 1: enc conv(k=3)+ReLU + addon 1x1+ReLU via HMMA (split-bf16 3-pass)
//   t-tile 128, 8 warps (4 t-quarters x 2 ch-halves), warp tile 32x32
//   78 KB smem, <=128 regs -> 2 CTAs/SM
// ---------------------------------------------------------------------------
#define B1_ROWB 80
#define OFF_B1  0                       // x tile  [132][80B] (16hi|16lo)
#define OFF_A1  10560                   // w1      [3][64][80B]
#define OFF_A2  25920                   // w2      [64][272B]
#define OFF_B2  43328                   // f1 tile [128][272B] (64hi|64lo)
#define ENC_DYN 78144

__global__ void __launch_bounds__(256, 2)
enc_addon_kernel(const float* __restrict__ x)
{
    extern __shared__ char esm[];
    __shared__ float s_g2[128];

    const int b   = blockIdx.y;
    const int t0  = blockIdx.x * 128;
    const int tid = threadIdx.x;
    const int lane = tid & 31;
    const int wid  = tid >> 5;
    const int wm  = wid & 3;        // t quarter (32 t)
    const int wn  = wid >> 2;       // ch half (32 ch)
    const int sub = lane >> 3;
    const int lr  = lane & 7;
    const int g   = lane >> 2;
    const int tig = lane & 3;

    const uint32_t b1_u = smem_u32(esm) + OFF_B1;
    const uint32_t a1_u = smem_u32(esm) + OFF_A1;
    const uint32_t a2_u = smem_u32(esm) + OFF_A2;
    const uint32_t b2_u = smem_u32(esm) + OFF_B2;

    // ---- load + split x tile: [130 rows][16hi|16lo] ----
    for (int idx = tid; idx < 16 * 130; idx += 256) {
        int i = idx / 130, r = idx - i * 130;
        int t = t0 + r;
        float v = (t < L_) ? x[(b * FIN + i) * L_ + t] : 0.f;
        __nv_bfloat16 hi = __float2bfloat16(v);
        __nv_bfloat16 lo = __float2bfloat16(v - __bfloat162float(hi));
        char* row = esm + OFF_B1 + r * B1_ROWB;
        *reinterpret_cast<__nv_bfloat16*>(row + i * 2)      = hi;
        *reinterpret_cast<__nv_bfloat16*>(row + 32 + i * 2) = lo;
    }
    for (int idx = tid; idx < 3 * 64 * 16; idx += 256) {
        int q = idx & 15, ch = (idx >> 4) & 63, tap = idx >> 10;
        *reinterpret_cast<uint32_t*>(esm + OFF_A1 + tap * (64 * B1_ROWB)
                                     + ch * B1_ROWB + q * 4) =
            reinterpret_cast<const uint32_t*>(d_w1)[idx];
    }
    for (int idx = tid; idx < 64 * 64; idx += 256) {
        int q = idx & 63, ch2 = idx >> 6;
        *reinterpret_cast<uint32_t*>(esm + OFF_A2 + ch2 * 272 + q * 4) =
            reinterpret_cast<const uint32_t*>(d_w2)[idx];
    }
    if (tid < 128) s_g2[tid] = 0.f;
    __syncthreads();

    // ---- stage 1: conv k=3 (M=128 t, N=64 ch; warp tile 32x32) ----
    float acc1[2][4][4];
#pragma unroll
    for (int mt = 0; mt < 2; mt++)
#pragma unroll
        for (int nt = 0; nt < 4; nt++)
#pragma unroll
            for (int e = 0; e < 4; e++) acc1[mt][nt][e] = 0.f;

    const uint32_t a1row  = (uint32_t)(wm * 32 + (sub & 1) * 8 + lr);
    const uint32_t a1colq = (uint32_t)((sub >> 1) * 16);
    const uint32_t w1row  = (uint32_t)((wn * 32 + (sub >> 1) * 8 + lr) * B1_ROWB
                                       + (sub & 1) * 16);

#pragma unroll
    for (int tap = 0; tap < 3; tap++) {
#pragma unroll
        for (int pass = 0; pass < 3; pass++) {
            const uint32_t colA = (pass == 2) ? 32u : 0u;
            const uint32_t colB = (pass == 1) ? 32u : 0u;
            uint32_t bf[4][2];
            const uint32_t wb = a1_u + tap * (64 * B1_ROWB) + w1row + colB;
            LDSM4(bf[0][0], bf[0][1], bf[1][0], bf[1][1], wb);
            LDSM4(bf[2][0], bf[2][1], bf[3][0], bf[3][1], wb + 16 * B1_ROWB);
#pragma unroll
            for (int mt = 0; mt < 2; mt++) {
                uint32_t a[4];
                LDSM4(a[0], a[1], a[2], a[3],
                      b1_u + (a1row + mt * 16 + tap) * B1_ROWB + a1colq + colA);
#pragma unroll
                for (int nt = 0; nt < 4; nt++)
                    mma16816(acc1[mt][nt], a, bf[nt]);
            }
        }
    }

    // ---- epilogue 1: relu, split hi/lo -> B2 [t][64hi|64lo] ----
#pragma unroll
    for (int mt = 0; mt < 2; mt++) {
#pragma unroll
        for (int nt = 0; nt < 4; nt++) {
#pragma unroll
            for (int eh = 0; eh < 2; eh++) {
                const int t  = wm * 32 + mt * 16 + g + eh * 8;
                const int ch = wn * 32 + nt * 8 + tig * 2;
                float v0 = fmaxf(acc1[mt][nt][eh * 2 + 0], 0.f);
                float v1 = fmaxf(acc1[mt][nt][eh * 2 + 1], 0.f);
                __nv_bfloat16 h0 = __float2bfloat16(v0);
                __nv_bfloat16 h1 = __float2bfloat16(v1);
                __nv_bfloat16 l0 = __float2bfloat16(v0 - __bfloat162float(h0));
                __nv_bfloat16 l1 = __float2bfloat16(v1 - __bfloat162float(h1));
                uint32_t hp = (uint32_t)__bfloat16_as_ushort(h0)
                            | ((uint32_t)__bfloat16_as_ushort(h1) << 16);
                uint32_t lp = (uint32_t)__bfloat16_as_ushort(l0)
                            | ((uint32_t)__bfloat16_as_ushort(l1) << 16);
                char* row = esm + OFF_B2 + t * 272;
                *reinterpret_cast<uint32_t*>(row + ch * 2)       = hp;
                *reinterpret_cast<uint32_t*>(row + 128 + ch * 2) = lp;
            }
        }
    }
    __syncthreads();

    // ---- stage 2: 1x1 addon ----
    float acc2[2][4][4];
#pragma unroll
    for (int mt = 0; mt < 2; mt++)
#pragma unroll
        for (int nt = 0; nt < 4; nt++)
#pragma unroll
            for (int e = 0; e < 4; e++) acc2[mt][nt][e] = 0.f;

    const uint32_t a2base = b2_u + (uint32_t)((wm * 32 + (sub & 1) * 8 + lr) * 272
                                              + (sub >> 1) * 16);
    const uint32_t w2base = a2_u + (uint32_t)((wn * 32 + (sub >> 1) * 8 + lr) * 272
                                              + (sub & 1) * 16);

#pragma unroll
    for (int step = 0; step < 12; step++) {
        const int kc   = step & 3;
        const int pass = step >> 2;            // 0: hh, 1: h*lo(w), 2: lo(f)*h
        const uint32_t colA = (pass == 2) ? (128u + kc * 32u) : (kc * 32u);
        const uint32_t colB = (pass == 1) ? (128u + kc * 32u) : (kc * 32u);
        uint32_t bf[4][2];
        LDSM4(bf[0][0], bf[0][1], bf[1][0], bf[1][1], w2base + colB);
        LDSM4(bf[2][0], bf[2][1], bf[3][0], bf[3][1], w2base + colB + 16 * 272);
#pragma unroll
        for (int mt = 0; mt < 2; mt++) {
            uint32_t a[4];
            LDSM4(a[0], a[1], a[2], a[3], a2base + mt * (16 * 272) + colA);
#pragma unroll
            for (int nt = 0; nt < 4; nt++)
                mma16816(acc2[mt][nt], a, bf[nt]);
        }
    }

    // ---- epilogue 2: relu, round bf16, store f, accumulate g ----
#pragma unroll
    for (int mt = 0; mt < 2; mt++) {
#pragma unroll
        for (int eh = 0; eh < 2; eh++) {
            const int t  = wm * 32 + mt * 16 + g + eh * 8;
            const int tg = t0 + t;
            float gp = 0.f;
#pragma unroll
            for (int nt = 0; nt < 4; nt++) {
                const int ch = wn * 32 + nt * 8 + tig * 2;
                float v0 = fmaxf(acc2[mt][nt][eh * 2 + 0], 0.f);
                float v1 = fmaxf(acc2[mt][nt][eh * 2 + 1], 0.f);
                __nv_bfloat162 h2 = __floats2bfloat162_rn(v0, v1);
                float r0 = __bfloat162float(__low2bfloat16(h2));
                float r1 = __bfloat162float(__high2bfloat16(h2));
                gp += r0 * r0 + r1 * r1;
                if (tg < L1_)
                    *reinterpret_cast<uint32_t*>(
                        d_fT + ((size_t)b * TPAD + tg) * LAT + ch) =
                        *reinterpret_cast<uint32_t*>(&h2);
            }
            atomicAdd(&s_g2[t], gp);
        }
    }
    __syncthreads();
    if (tid < 128 && t0 + tid < L1_) d_g[b * TPAD + t0 + tid] = s_g2[tid];
}

// ---------------------------------------------------------------------------
// Kernel 2: HMMA GEMM + distance + min-reduce (round-8 config, reverted)
//   MBW = m16-blocks per warp, NWN = warps along N (8 warps total)
//   CTA M = MBW*(8/NWN)*16, CTA N = 256
// ---------------------------------------------------------------------------
#define NT_       256
#define FROWS     272
#define ROWB      144
#define SF_BYTES  (FROWS * ROWB)

template<int MBW, int NWN>
__global__ void __launch_bounds__(256, 1)
gemm_min_kernel(unsigned* __restrict__ md, int p0)
{
    constexpr int NWM  = 8 / NWN;
    constexpr int MB16 = MBW * NWM * 16;
    constexpr int NTW  = 256 / (NWN * 8);
    constexpr int SP_TAPB = MB16 * ROWB;
    constexpr int SP_BYTESB = 4 * SP_TAPB;
    constexpr int LD_ITEMS = 4 * MB16 * 8;

    extern __shared__ char dynsm[];
    char* sf = dynsm;
    char* sp = dynsm + SF_BYTES;

    __shared__ float    s_g[FROWS];
    __shared__ float    s2s[NT_];
    __shared__ float    s_p2[128];
    __shared__ unsigned s_md[128];

    const int b   = blockIdx.y;
    const int t0  = blockIdx.x * NT_;
    const int tid = threadIdx.x;
    const int lane = tid & 31;
    const int wid  = tid >> 5;
    const int wm = wid / NWN;
    const int wn = wid % NWN;
    const int sub = lane >> 3;
    const int lr  = lane & 7;

    const uint32_t sf_u32 = smem_u32(sf);
    const uint32_t sp_u32 = smem_u32(sp);

    const __nv_bfloat16* fT = d_fT + (size_t)b * TPAD * LAT;
    for (int i = tid; i < FROWS * 8; i += 256) {
        int r = i >> 3, seg = i & 7;
        cp16(sf_u32 + r * ROWB + seg * 16,
             fT + (size_t)(t0 + r) * LAT + seg * 8);
    }
    for (int i = tid; i < LD_ITEMS; i += 256) {
        int j = i / (MB16 * 8), rs = i % (MB16 * 8);
        int r = rs >> 3, seg = rs & 7;
        cp16(sp_u32 + j * SP_TAPB + r * ROWB + seg * 16,
             d_protA + ((size_t)(j * 256 + p0 + r)) * LAT + seg * 8);
    }
    CP_COMMIT();

    for (int i = tid; i < FROWS; i += 256) s_g[i] = d_g[b * TPAD + t0 + i];
    if (tid < 128) {
        s_p2[tid] = d_p2[p0 + tid];
        s_md[tid] = 0x7f800000u;
    }
    CP_WAIT0();
    __syncthreads();

    if (tid < NT_) {
        float s = 0.f;
#pragma unroll
        for (int k = 0; k < KP; k++) s += s_g[tid + k];
        s2s[tid] = s;
    }

    float acc[MBW][NTW][4];
#pragma unroll
    for (int mt = 0; mt < MBW; mt++)
#pragma unroll
        for (int nt = 0; nt < NTW; nt++)
#pragma unroll
            for (int e = 0; e < 4; e++) acc[mt][nt][e] = 0.f;

    const uint32_t a_off = (uint32_t)((wm * MBW * 16 + (sub & 1) * 8 + lr) * ROWB
                                      + (sub >> 1) * 16);
    const uint32_t b_off = (uint32_t)((wn * NTW * 8 + (sub >> 1) * 8 + lr) * ROWB
                                      + (sub & 1) * 16);

    for (int ph = 0; ph < 4; ph++) {
        const uint32_t buf = sp_u32 + (ph & 1) * SP_BYTESB;

        if (ph < 3) {
            const uint32_t nbuf = sp_u32 + ((ph + 1) & 1) * SP_BYTESB;
            for (int i = tid; i < LD_ITEMS; i += 256) {
                int j = i / (MB16 * 8), rs = i % (MB16 * 8);
                int r = rs >> 3, seg = rs & 7;
                cp16(nbuf + j * SP_TAPB + r * ROWB + seg * 16,
                     d_protA + ((size_t)(((ph + 1) * 4 + j) * 256 + p0 + r)) * LAT
                             + seg * 8);
            }
            CP_COMMIT();
        }

#pragma unroll
        for (int j = 0; j < 4; j++) {
            const int kk = ph * 4 + j;
            const uint32_t abase = buf + j * SP_TAPB + a_off;
            const uint32_t bbase = sf_u32 + kk * ROWB + b_off;
#pragma unroll
            for (int cc = 0; cc < 4; cc++) {
                uint32_t a[MBW][4], bf[NTW][2];
#pragma unroll
                for (int mb = 0; mb < MBW; mb++)
                    LDSM4(a[mb][0], a[mb][1], a[mb][2], a[mb][3],
                          abase + mb * (16 * ROWB) + cc * 32);
#pragma unroll
                for (int np = 0; np < NTW / 2; np++)
                    LDSM4(bf[2*np][0], bf[2*np][1], bf[2*np+1][0], bf[2*np+1][1],
                          bbase + np * (16 * ROWB) + cc * 32);
#pragma unroll
                for (int mt = 0; mt < MBW; mt++)
#pragma unroll
                    for (int nt = 0; nt < NTW; nt++)
                        mma16816(acc[mt][nt], a[mt], bf[nt]);
            }
        }

        if (ph < 3) {
            CP_WAIT0();
            __syncthreads();
        }
    }

    // ---- epilogue: dist = relu(s2 - 2*xp + p2), min over t ----
    const int g   = lane >> 2;
    const int tig = lane & 3;
#pragma unroll
    for (int mt = 0; mt < MBW; mt++) {
#pragma unroll
        for (int half = 0; half < 2; half++) {
            const int pl = wm * MBW * 16 + mt * 16 + g + half * 8;
            const float pp = s_p2[pl];
            float mn = __int_as_float(0x7f800000);
#pragma unroll
            for (int nt = 0; nt < NTW; nt++) {
#pragma unroll
                for (int e = 0; e < 2; e++) {
                    const int col = wn * NTW * 8 + nt * 8 + tig * 2 + e;
                    if (t0 + col < LO) {
                        float xp = acc[mt][nt][half * 2 + e];
                        float dd = fmaxf(s2s[col] - 2.f * xp + pp, 0.f);
                        mn = fminf(mn, dd);
                    }
                }
            }
            atomicMin(&s_md[pl], __float_as_uint(mn));
        }
    }
    __syncthreads();
    if (tid < MB16 && p0 + tid < P_)
        atomicMin(&md[b * P_ + p0 + tid], s_md[tid]);
}

#define GEMM_DYN0 (SF_BYTES + 2 * 4 * 128 * ROWB)   // 186624
#define GEMM_DYN1 (SF_BYTES + 2 * 4 * 80  * ROWB)   // 131328

// ---------------------------------------------------------------------------
// Kernel 3: head — one block per batch, warp per class
// ---------------------------------------------------------------------------
__global__ void head_kernel(const float* __restrict__ lw,
                            float* __restrict__ out)
{
    __shared__ float acts[P_];
    const int b   = blockIdx.x;
    const int tid = threadIdx.x;     // 320
    const unsigned* mdb = (const unsigned*)(out + B_ * C_) + b * P_;

    if (tid < P_) {
        float m = __uint_as_float(mdb[tid]);
        acts[tid] = logf((m + 1.0f) / (m + EPS_));
    }
    __syncthreads();

    const int c    = tid >> 5;
    const int lane = tid & 31;
    float s = 0.f;
    for (int p = lane; p < P_; p += 32)
        s += acts[p] * lw[c * P_ + p];
#pragma unroll
    for (int o = 16; o; o >>= 1) s += __shfl_xor_sync(0xffffffffu, s, o);
    if (lane == 0) out[b * C_ + c] = s;
}

// ---------------------------------------------------------------------------
extern "C" void kernel_launch(void* const* d_in, const int* in_sizes, int n_in,
                              void* d_out, int out_size)
{
    const float* x       = (const float*)d_in[0];
    const float* enc_w   = (const float*)d_in[1];
    const float* addon_w = (const float*)d_in[2];
    const float* protos  = (const float*)d_in[3];
    const float* last_w  = (const float*)d_in[4];
    float* out = (float*)d_out;

    cudaFuncSetAttribute(enc_addon_kernel,
                         cudaFuncAttributeMaxDynamicSharedMemorySize, ENC_DYN);
    cudaFuncSetAttribute(gemm_min_kernel<4, 4>,
                         cudaFuncAttributeMaxDynamicSharedMemorySize, GEMM_DYN0);
    cudaFuncSetAttribute(gemm_min_kernel<5, 8>,
                         cudaFuncAttributeMaxDynamicSharedMemorySize, GEMM_DYN1);

    unsigned* md = (unsigned*)(out + B_ * C_);

    prep_kernel<<<PREP_GRID, 256>>>(protos, enc_w, addon_w, md);
    enc_addon_kernel<<<dim3(64, B_), 256, ENC_DYN>>>(x);
    gemm_min_kernel<4, 4><<<dim3(32, B_), 256, GEMM_DYN0>>>(md, 0);    // p 0-127
    gemm_min_kernel<5, 8><<<dim3(32, B_), 256, GEMM_DYN1>>>(md, 128);  // p 128-199
    head_kernel<<<B_, 320>>>(last_w, out);
}

// round 11
// speedup vs baseline: 1.1310x; 1.0300x over previous
#include <cuda_runtime.h>
#include <cuda_bf16.h>
#include <cstdint>

// ---------------------------------------------------------------------------
// ProtoTSNet on GB300 — round 11
//  - gemm: single launch (grid.z = p-chunk); 80-row chunk loads all 16 taps
//    once (223KB smem, zero mid-kernel syncs); 128-row chunk = proven R8 path
//  - enc/prep/head unchanged from round 10
//
// out[0..319]    = logits [32,10]
// out[320..6719] = min_distances [32,200]
// ---------------------------------------------------------------------------

#define B_     32
#define FIN    16
#define L_     8192
#define LAT    64
#define L1_    8190
#define P_     200
#define KP     16
#define LO     8175
#define C_     10
#define EPS_   1e-4f
#define TPAD   8224

// ---------------- static device scratch (allocation-free) -----------------
__device__ __nv_bfloat16 d_fT[B_ * TPAD * LAT];    // f [b][t][c], bf16
__device__ float         d_g [B_ * TPAD];          // sum_c f_bf16^2
__device__ __nv_bfloat16 d_protA[16 * 256 * LAT];  // protos [kk][p pad256][c]
__device__ float         d_p2[256];                // ||p||^2 (bf16-rounded)
__device__ __nv_bfloat16 d_w1[3 * 64 * 32];        // enc w  [tap][ch][16hi|16lo]
__device__ __nv_bfloat16 d_w2[64 * 128];           // addon w [ch2][64hi|64lo]

__device__ __forceinline__ uint32_t smem_u32(const void* p) {
    uint32_t a;
    asm("{ .reg .u64 t; cvta.to.shared.u64 t, %1; cvt.u32.u64 %0, t; }"
        : "=r"(a) : "l"(p));
    return a;
}
__device__ __forceinline__ void cp16(uint32_t s, const void* g) {
    asm volatile("cp.async.cg.shared.global [%0], [%1], 16;" :: "r"(s), "l"(g));
}
#define CP_COMMIT() asm volatile("cp.async.commit_group;" ::: "memory")
#define CP_WAIT0()  asm volatile("cp.async.wait_group 0;" ::: "memory")

__device__ __forceinline__ void mma16816(float* c, const uint32_t* a,
                                         const uint32_t* b)
{
    asm volatile(
        "mma.sync.aligned.m16n8k16.row.col.f32.bf16.bf16.f32 "
        "{%0,%1,%2,%3}, {%4,%5,%6,%7}, {%8,%9}, {%0,%1,%2,%3};"
        : "+f"(c[0]), "+f"(c[1]), "+f"(c[2]), "+f"(c[3])
        : "r"(a[0]), "r"(a[1]), "r"(a[2]), "r"(a[3]), "r"(b[0]), "r"(b[1]));
}
#define LDSM4(r0, r1, r2, r3, addr)                                           \
    asm volatile("ldmatrix.sync.aligned.m8n8.x4.shared.b16 {%0,%1,%2,%3},[%4];" \
        : "=r"(r0), "=r"(r1), "=r"(r2), "=r"(r3) : "r"(addr))

// ---------------------------------------------------------------------------
// Kernel 0: merged prep (block-range dispatch)
// ---------------------------------------------------------------------------
#define PREP_GRID 1305

__global__ void prep_kernel(const float* __restrict__ protos,
                            const float* __restrict__ ew,
                            const float* __restrict__ aw,
                            unsigned* __restrict__ md)
{
    const int blk = blockIdx.x;
    const int tid = threadIdx.x;

    if (blk < 1024) {                              // protA
        int idx = blk * 256 + tid;
        int c  = idx & 63;
        int pp = (idx >> 6) & 255;
        int kk = idx >> 14;
        float v = (pp < P_) ? protos[pp * (LAT * KP) + c * KP + kk] : 0.f;
        d_protA[idx] = __float2bfloat16(v);
    } else if (blk < 1224) {                       // p2
        const int p = blk - 1024;
        float s = 0.f;
        for (int i = tid; i < LAT * KP; i += 256) {
            float v = __bfloat162float(__float2bfloat16(protos[p * LAT * KP + i]));
            s += v * v;
        }
#pragma unroll
        for (int o = 16; o; o >>= 1) s += __shfl_xor_sync(0xffffffffu, s, o);
        __shared__ float red[8];
        if ((tid & 31) == 0) red[tid >> 5] = s;
        __syncthreads();
        if (tid == 0) {
            float ts = 0.f;
            for (int w = 0; w < 8; w++) ts += red[w];
            d_p2[p] = ts;
        }
    } else if (blk < 1249) {                       // init md
        int i = (blk - 1224) * 256 + tid;
        if (i < B_ * P_) md[i] = 0x7f800000u;
    } else if (blk < 1273) {                       // prep_w1
        int idx = (blk - 1249) * 256 + tid;
        if (idx < 3 * 64 * 32) {
            int pos = idx & 31, ch = (idx >> 5) & 63, tap = idx >> 11;
            int i = pos & 15;
            float w = ew[ch * 48 + i * 3 + tap];
            __nv_bfloat16 hi = __float2bfloat16(w);
            if (pos < 16) d_w1[idx] = hi;
            else          d_w1[idx] = __float2bfloat16(w - __bfloat162float(hi));
        }
    } else {                                       // prep_w2
        int idx = (blk - 1273) * 256 + tid;
        if (idx < 64 * 128) {
            int pos = idx & 127, ch2 = idx >> 7;
            int c = pos & 63;
            float w = aw[ch2 * 64 + c];
            __nv_bfloat16 hi = __float2bfloat16(w);
            if (pos < 64) d_w2[idx] = hi;
            else          d_w2[idx] = __float2bfloat16(w - __bfloat162float(hi));
        }
    }
}

// ---------------------------------------------------------------------------
// Kernel 1: enc conv(k=3)+ReLU + addon 1x1+ReLU via HMMA (split-bf16 3-pass)
//   t-tile 128, 8 warps, warp tile 32x32, 78 KB smem -> 2 CTAs/SM
// ---------------------------------------------------------------------------
#define B1_ROWB 80
#define OFF_B1  0
#define OFF_A1  10560
#define OFF_A2  25920
#define OFF_B2  43328
#define ENC_DYN 78144

__global__ void __launch_bounds__(256, 2)
enc_addon_kernel(const float* __restrict__ x)
{
    extern __shared__ char esm[];
    __shared__ float s_g2[128];

    const int b   = blockIdx.y;
    const int t0  = blockIdx.x * 128;
    const int tid = threadIdx.x;
    const int lane = tid & 31;
    const int wid  = tid >> 5;
    const int wm  = wid & 3;
    const int wn  = wid >> 2;
    const int sub = lane >> 3;
    const int lr  = lane & 7;
    const int g   = lane >> 2;
    const int tig = lane & 3;

    const uint32_t b1_u = smem_u32(esm) + OFF_B1;
    const uint32_t a1_u = smem_u32(esm) + OFF_A1;
    const uint32_t a2_u = smem_u32(esm) + OFF_A2;
    const uint32_t b2_u = smem_u32(esm) + OFF_B2;

    for (int idx = tid; idx < 16 * 130; idx += 256) {
        int i = idx / 130, r = idx - i * 130;
        int t = t0 + r;
        float v = (t < L_) ? x[(b * FIN + i) * L_ + t] : 0.f;
        __nv_bfloat16 hi = __float2bfloat16(v);
        __nv_bfloat16 lo = __float2bfloat16(v - __bfloat162float(hi));
        char* row = esm + OFF_B1 + r * B1_ROWB;
        *reinterpret_cast<__nv_bfloat16*>(row + i * 2)      = hi;
        *reinterpret_cast<__nv_bfloat16*>(row + 32 + i * 2) = lo;
    }
    for (int idx = tid; idx < 3 * 64 * 16; idx += 256) {
        int q = idx & 15, ch = (idx >> 4) & 63, tap = idx >> 10;
        *reinterpret_cast<uint32_t*>(esm + OFF_A1 + tap * (64 * B1_ROWB)
                                     + ch * B1_ROWB + q * 4) =
            reinterpret_cast<const uint32_t*>(d_w1)[idx];
    }
    for (int idx = tid; idx < 64 * 64; idx += 256) {
        int q = idx & 63, ch2 = idx >> 6;
        *reinterpret_cast<uint32_t*>(esm + OFF_A2 + ch2 * 272 + q * 4) =
            reinterpret_cast<const uint32_t*>(d_w2)[idx];
    }
    if (tid < 128) s_g2[tid] = 0.f;
    __syncthreads();

    // ---- stage 1: conv k=3 ----
    float acc1[2][4][4];
#pragma unroll
    for (int mt = 0; mt < 2; mt++)
#pragma unroll
        for (int nt = 0; nt < 4; nt++)
#pragma unroll
            for (int e = 0; e < 4; e++) acc1[mt][nt][e] = 0.f;

    const uint32_t a1row  = (uint32_t)(wm * 32 + (sub & 1) * 8 + lr);
    const uint32_t a1colq = (uint32_t)((sub >> 1) * 16);
    const uint32_t w1row  = (uint32_t)((wn * 32 + (sub >> 1) * 8 + lr) * B1_ROWB
                                       + (sub & 1) * 16);

#pragma unroll
    for (int tap = 0; tap < 3; tap++) {
#pragma unroll
        for (int pass = 0; pass < 3; pass++) {
            const uint32_t colA = (pass == 2) ? 32u : 0u;
            const uint32_t colB = (pass == 1) ? 32u : 0u;
            uint32_t bf[4][2];
            const uint32_t wb = a1_u + tap * (64 * B1_ROWB) + w1row + colB;
            LDSM4(bf[0][0], bf[0][1], bf[1][0], bf[1][1], wb);
            LDSM4(bf[2][0], bf[2][1], bf[3][0], bf[3][1], wb + 16 * B1_ROWB);
#pragma unroll
            for (int mt = 0; mt < 2; mt++) {
                uint32_t a[4];
                LDSM4(a[0], a[1], a[2], a[3],
                      b1_u + (a1row + mt * 16 + tap) * B1_ROWB + a1colq + colA);
#pragma unroll
                for (int nt = 0; nt < 4; nt++)
                    mma16816(acc1[mt][nt], a, bf[nt]);
            }
        }
    }

    // ---- epilogue 1 ----
#pragma unroll
    for (int mt = 0; mt < 2; mt++) {
#pragma unroll
        for (int nt = 0; nt < 4; nt++) {
#pragma unroll
            for (int eh = 0; eh < 2; eh++) {
                const int t  = wm * 32 + mt * 16 + g + eh * 8;
                const int ch = wn * 32 + nt * 8 + tig * 2;
                float v0 = fmaxf(acc1[mt][nt][eh * 2 + 0], 0.f);
                float v1 = fmaxf(acc1[mt][nt][eh * 2 + 1], 0.f);
                __nv_bfloat16 h0 = __float2bfloat16(v0);
                __nv_bfloat16 h1 = __float2bfloat16(v1);
                __nv_bfloat16 l0 = __float2bfloat16(v0 - __bfloat162float(h0));
                __nv_bfloat16 l1 = __float2bfloat16(v1 - __bfloat162float(h1));
                uint32_t hp = (uint32_t)__bfloat16_as_ushort(h0)
                            | ((uint32_t)__bfloat16_as_ushort(h1) << 16);
                uint32_t lp = (uint32_t)__bfloat16_as_ushort(l0)
                            | ((uint32_t)__bfloat16_as_ushort(l1) << 16);
                char* row = esm + OFF_B2 + t * 272;
                *reinterpret_cast<uint32_t*>(row + ch * 2)       = hp;
                *reinterpret_cast<uint32_t*>(row + 128 + ch * 2) = lp;
            }
        }
    }
    __syncthreads();

    // ---- stage 2: 1x1 addon ----
    float acc2[2][4][4];
#pragma unroll
    for (int mt = 0; mt < 2; mt++)
#pragma unroll
        for (int nt = 0; nt < 4; nt++)
#pragma unroll
            for (int e = 0; e < 4; e++) acc2[mt][nt][e] = 0.f;

    const uint32_t a2base = b2_u + (uint32_t)((wm * 32 + (sub & 1) * 8 + lr) * 272
                                              + (sub >> 1) * 16);
    const uint32_t w2base = a2_u + (uint32_t)((wn * 32 + (sub >> 1) * 8 + lr) * 272
                                              + (sub & 1) * 16);

#pragma unroll
    for (int step = 0; step < 12; step++) {
        const int kc   = step & 3;
        const int pass = step >> 2;
        const uint32_t colA = (pass == 2) ? (128u + kc * 32u) : (kc * 32u);
        const uint32_t colB = (pass == 1) ? (128u + kc * 32u) : (kc * 32u);
        uint32_t bf[4][2];
        LDSM4(bf[0][0], bf[0][1], bf[1][0], bf[1][1], w2base + colB);
        LDSM4(bf[2][0], bf[2][1], bf[3][0], bf[3][1], w2base + colB + 16 * 272);
#pragma unroll
        for (int mt = 0; mt < 2; mt++) {
            uint32_t a[4];
            LDSM4(a[0], a[1], a[2], a[3], a2base + mt * (16 * 272) + colA);
#pragma unroll
            for (int nt = 0; nt < 4; nt++)
                mma16816(acc2[mt][nt], a, bf[nt]);
        }
    }

    // ---- epilogue 2 ----
#pragma unroll
    for (int mt = 0; mt < 2; mt++) {
#pragma unroll
        for (int eh = 0; eh < 2; eh++) {
            const int t  = wm * 32 + mt * 16 + g + eh * 8;
            const int tg = t0 + t;
            float gp = 0.f;
#pragma unroll
            for (int nt = 0; nt < 4; nt++) {
                const int ch = wn * 32 + nt * 8 + tig * 2;
                float v0 = fmaxf(acc2[mt][nt][eh * 2 + 0], 0.f);
                float v1 = fmaxf(acc2[mt][nt][eh * 2 + 1], 0.f);
                __nv_bfloat162 h2 = __floats2bfloat162_rn(v0, v1);
                float r0 = __bfloat162float(__low2bfloat16(h2));
                float r1 = __bfloat162float(__high2bfloat16(h2));
                gp += r0 * r0 + r1 * r1;
                if (tg < L1_)
                    *reinterpret_cast<uint32_t*>(
                        d_fT + ((size_t)b * TPAD + tg) * LAT + ch) =
                        *reinterpret_cast<uint32_t*>(&h2);
            }
            atomicAdd(&s_g2[t], gp);
        }
    }
    __syncthreads();
    if (tid < 128 && t0 + tid < L1_) d_g[b * TPAD + t0 + tid] = s_g2[tid];
}

// ---------------------------------------------------------------------------
// Kernel 2: HMMA GEMM + distance + min-reduce (single launch, grid.z chunks)
//   z=0: M=128 (MBW=4, NWN=4), 4 phases x 4 taps, double-buffered
//   z=1: M=80  (MBW=5, NWN=8), 1 phase x 16 taps, single buffer, no syncs
// ---------------------------------------------------------------------------
#define NT_       256
#define FROWS     272
#define ROWB      144
#define SF_BYTES  (FROWS * ROWB)           // 39168
#define GEMM_DYN  (SF_BYTES + 16 * 80 * ROWB)  // 223488 (max of both variants)

template<int MBW, int NWN, int TPP, int NBUF>
__device__ __forceinline__ void gemm_body(unsigned* __restrict__ md, int p0,
                                          char* dynsm, float* s_g, float* s2s,
                                          float* s_p2, unsigned* s_md)
{
    constexpr int NWM    = 8 / NWN;
    constexpr int MB16   = MBW * NWM * 16;
    constexpr int NTW    = 256 / (NWN * 8);
    constexpr int PHASES = 16 / TPP;
    constexpr int SP_TAPB = MB16 * ROWB;
    constexpr int SP_PH   = TPP * SP_TAPB;
    constexpr int LD_ITEMS = TPP * MB16 * 8;

    char* sf = dynsm;
    char* sp = dynsm + SF_BYTES;

    const int b   = blockIdx.y;
    const int t0  = blockIdx.x * NT_;
    const int tid = threadIdx.x;
    const int lane = tid & 31;
    const int wid  = tid >> 5;
    const int wm = wid / NWN;
    const int wn = wid % NWN;
    const int sub = lane >> 3;
    const int lr  = lane & 7;

    const uint32_t sf_u32 = smem_u32(sf);
    const uint32_t sp_u32 = smem_u32(sp);

    const __nv_bfloat16* fT = d_fT + (size_t)b * TPAD * LAT;
    for (int i = tid; i < FROWS * 8; i += 256) {
        int r = i >> 3, seg = i & 7;
        cp16(sf_u32 + r * ROWB + seg * 16,
             fT + (size_t)(t0 + r) * LAT + seg * 8);
    }
    for (int i = tid; i < LD_ITEMS; i += 256) {
        int j = i / (MB16 * 8), rs = i % (MB16 * 8);
        int r = rs >> 3, seg = rs & 7;
        cp16(sp_u32 + j * SP_TAPB + r * ROWB + seg * 16,
             d_protA + ((size_t)(j * 256 + p0 + r)) * LAT + seg * 8);
    }
    CP_COMMIT();

    for (int i = tid; i < FROWS; i += 256) s_g[i] = d_g[b * TPAD + t0 + i];
    if (tid < 128) {
        s_p2[tid] = d_p2[p0 + tid];
        s_md[tid] = 0x7f800000u;
    }
    CP_WAIT0();
    __syncthreads();

    if (tid < NT_) {
        float s = 0.f;
#pragma unroll
        for (int k = 0; k < KP; k++) s += s_g[tid + k];
        s2s[tid] = s;
    }

    float acc[MBW][NTW][4];
#pragma unroll
    for (int mt = 0; mt < MBW; mt++)
#pragma unroll
        for (int nt = 0; nt < NTW; nt++)
#pragma unroll
            for (int e = 0; e < 4; e++) acc[mt][nt][e] = 0.f;

    const uint32_t a_off = (uint32_t)((wm * MBW * 16 + (sub & 1) * 8 + lr) * ROWB
                                      + (sub >> 1) * 16);
    const uint32_t b_off = (uint32_t)((wn * NTW * 8 + (sub >> 1) * 8 + lr) * ROWB
                                      + (sub & 1) * 16);

#pragma unroll
    for (int ph = 0; ph < PHASES; ph++) {
        const uint32_t buf = sp_u32 + ((NBUF == 2) ? (ph & 1) : 0) * SP_PH;

        if (NBUF == 2 && ph < PHASES - 1) {
            const uint32_t nbuf = sp_u32 + ((ph + 1) & 1) * SP_PH;
            for (int i = tid; i < LD_ITEMS; i += 256) {
                int j = i / (MB16 * 8), rs = i % (MB16 * 8);
                int r = rs >> 3, seg = rs & 7;
                cp16(nbuf + j * SP_TAPB + r * ROWB + seg * 16,
                     d_protA + ((size_t)(((ph + 1) * TPP + j) * 256 + p0 + r)) * LAT
                             + seg * 8);
            }
            CP_COMMIT();
        }

#pragma unroll
        for (int j = 0; j < TPP; j++) {
            const int kk = ph * TPP + j;
            const uint32_t abase = buf + j * SP_TAPB + a_off;
            const uint32_t bbase = sf_u32 + kk * ROWB + b_off;
#pragma unroll
            for (int cc = 0; cc < 4; cc++) {
                uint32_t a[MBW][4], bf[NTW][2];
#pragma unroll
                for (int mb = 0; mb < MBW; mb++)
                    LDSM4(a[mb][0], a[mb][1], a[mb][2], a[mb][3],
                          abase + mb * (16 * ROWB) + cc * 32);
#pragma unroll
                for (int np = 0; np < NTW / 2; np++)
                    LDSM4(bf[2*np][0], bf[2*np][1], bf[2*np+1][0], bf[2*np+1][1],
                          bbase + np * (16 * ROWB) + cc * 32);
#pragma unroll
                for (int mt = 0; mt < MBW; mt++)
#pragma unroll
                    for (int nt = 0; nt < NTW; nt++)
                        mma16816(acc[mt][nt], a[mt], bf[nt]);
            }
        }

        if (NBUF == 2 && ph < PHASES - 1) {
            CP_WAIT0();
            __syncthreads();
        }
    }

    // ---- epilogue: dist = relu(s2 - 2*xp + p2), min over t ----
    const int g   = lane >> 2;
    const int tig = lane & 3;
#pragma unroll
    for (int mt = 0; mt < MBW; mt++) {
#pragma unroll
        for (int half = 0; half < 2; half++) {
            const int pl = wm * MBW * 16 + mt * 16 + g + half * 8;
            const float pp = s_p2[pl];
            float mn = __int_as_float(0x7f800000);
#pragma unroll
            for (int nt = 0; nt < NTW; nt++) {
#pragma unroll
                for (int e = 0; e < 2; e++) {
                    const int col = wn * NTW * 8 + nt * 8 + tig * 2 + e;
                    if (t0 + col < LO) {
                        float xp = acc[mt][nt][half * 2 + e];
                        float dd = fmaxf(s2s[col] - 2.f * xp + pp, 0.f);
                        mn = fminf(mn, dd);
                    }
                }
            }
            atomicMin(&s_md[pl], __float_as_uint(mn));
        }
    }
    __syncthreads();
    if (tid < MB16 && p0 + tid < P_)
        atomicMin(&md[b * P_ + p0 + tid], s_md[tid]);
}

__global__ void __launch_bounds__(256, 1)
gemm_min_kernel(unsigned* __restrict__ md)
{
    extern __shared__ char dynsm[];
    __shared__ float    s_g[FROWS];
    __shared__ float    s2s[NT_];
    __shared__ float    s_p2[128];
    __shared__ unsigned s_md[128];

    if (blockIdx.z == 0)
        gemm_body<4, 4, 4, 2>(md, 0,   dynsm, s_g, s2s, s_p2, s_md);
    else
        gemm_body<5, 8, 16, 1>(md, 128, dynsm, s_g, s2s, s_p2, s_md);
}

// ---------------------------------------------------------------------------
// Kernel 3: head — one block per batch, warp per class
// ---------------------------------------------------------------------------
__global__ void head_kernel(const float* __restrict__ lw,
                            float* __restrict__ out)
{
    __shared__ float acts[P_];
    const int b   = blockIdx.x;
    const int tid = threadIdx.x;     // 320
    const unsigned* mdb = (const unsigned*)(out + B_ * C_) + b * P_;

    if (tid < P_) {
        float m = __uint_as_float(mdb[tid]);
        acts[tid] = logf((m + 1.0f) / (m + EPS_));
    }
    __syncthreads();

    const int c    = tid >> 5;
    const int lane = tid & 31;
    float s = 0.f;
    for (int p = lane; p < P_; p += 32)
        s += acts[p] * lw[c * P_ + p];
#pragma unroll
    for (int o = 16; o; o >>= 1) s += __shfl_xor_sync(0xffffffffu, s, o);
    if (lane == 0) out[b * C_ + c] = s;
}

// ---------------------------------------------------------------------------
extern "C" void kernel_launch(void* const* d_in, const int* in_sizes, int n_in,
                              void* d_out, int out_size)
{
    const float* x       = (const float*)d_in[0];
    const float* enc_w   = (const float*)d_in[1];
    const float* addon_w = (const float*)d_in[2];
    const float* protos  = (const float*)d_in[3];
    const float* last_w  = (const float*)d_in[4];
    float* out = (float*)d_out;

    cudaFuncSetAttribute(enc_addon_kernel,
                         cudaFuncAttributeMaxDynamicSharedMemorySize, ENC_DYN);
    cudaFuncSetAttribute(gemm_min_kernel,
                         cudaFuncAttributeMaxDynamicSharedMemorySize, GEMM_DYN);

    unsigned* md = (unsigned*)(out + B_ * C_);

    prep_kernel<<<PREP_GRID, 256>>>(protos, enc_w, addon_w, md);
    enc_addon_kernel<<<dim3(64, B_), 256, ENC_DYN>>>(x);
    gemm_min_kernel<<<dim3(32, B_, 2), 256, GEMM_DYN>>>(md);
    head_kernel<<<B_, 320>>>(last_w, out);
}